// round 1
// baseline (speedup 1.0000x reference)
#include <cuda_runtime.h>
#include <cuda_bf16.h>
#include <math.h>

// Problem constants (fixed by the dataset)
#define B      65536
#define D_IN   512
#define D_H    512
#define D_OUT  128
#define N_EXP  16

#define TILE_M 128
// max padded rows: every expert segment padded up to a multiple of TILE_M
#define MAXP   (B + N_EXP * TILE_M)      // 67584
#define MT1    (MAXP / TILE_M)           // 528 row tiles (exact)

// ---------------- device scratch (static, allocation-free) ----------------
__device__ float g_h[(size_t)MAXP * D_H];   // ~138 MB sorted hidden activations
__device__ int   g_counts[N_EXP];
__device__ int   g_cursor[N_EXP];
__device__ int   g_start[N_EXP + 1];        // padded segment starts
__device__ int   g_sorted[MAXP];            // sorted position -> original row

// ---------------- routing ----------------
__global__ void r0_zero() {
    int t = threadIdx.x;
    if (t < N_EXP) { g_counts[t] = 0; g_cursor[t] = 0; }
}

__global__ void r1_count(const int* __restrict__ num, const int* __restrict__ c) {
    __shared__ int h[N_EXP];
    int tid = threadIdx.x;
    if (tid < N_EXP) h[tid] = 0;
    __syncthreads();
    int i = blockIdx.x * blockDim.x + tid;
    if (i < B) {
        int e = c[num[i]];
        atomicAdd(&h[e], 1);
    }
    __syncthreads();
    if (tid < N_EXP && h[tid]) atomicAdd(&g_counts[tid], h[tid]);
}

__global__ void r2_scan() {
    // single thread: 16 iterations, trivial
    int s = 0;
    g_start[0] = 0;
    for (int e = 0; e < N_EXP; e++) {
        int padded = (g_counts[e] + TILE_M - 1) & ~(TILE_M - 1);
        s += padded;
        g_start[e + 1] = s;
    }
}

__global__ void r3_scatter(const int* __restrict__ num, const int* __restrict__ c) {
    int i = blockIdx.x * blockDim.x + threadIdx.x;
    if (i >= B) return;
    int e = c[num[i]];
    unsigned lane = threadIdx.x & 31;
    unsigned mask = __match_any_sync(0xffffffffu, e);
    int leader = __ffs(mask) - 1;
    int rank = __popc(mask & ((1u << lane) - 1u));
    int base = 0;
    if ((int)lane == leader) base = atomicAdd(&g_cursor[e], __popc(mask));
    base = __shfl_sync(0xffffffffu, base, leader);
    g_sorted[g_start[e] + base + rank] = i;
}

// ---------------- GEMM1: h = relu(x[sorted] @ W1 + b1), write sorted ----------------
// 128x128 tile, BK=8, 256 threads, 8x8 per thread
__global__ __launch_bounds__(256) void gemm1(const float* __restrict__ x,
                                             const float* __restrict__ W1,
                                             const float* __restrict__ b1) {
    __shared__ float As[8][TILE_M];
    __shared__ float Bs[8][128];
    __shared__ int   rows[TILE_M];

    const int tid = threadIdx.x;
    const int bn  = blockIdx.x;      // 0..3 (column tile of D_H)
    const int bm  = blockIdx.y;      // 0..527 (sorted row tile)
    const int p0  = bm * TILE_M;

    if (tid < TILE_M) {
        int r = g_sorted[p0 + tid];
        rows[tid] = min(max(r, 0), B - 1);   // clamp stale/garbage padding entries
    }
    __syncthreads();

    const int ty = tid >> 4;         // 0..15
    const int tx = tid & 15;         // 0..15

    // load map
    const int arow = tid >> 1;           // 0..127
    const int acol = (tid & 1) * 4;      // 0 or 4
    const int brow = tid >> 5;           // 0..7
    const int bcol = (tid & 31) * 4;     // 0..124

    const float* xrow = x + (size_t)rows[arow] * D_IN;

    float bb[8];
#pragma unroll
    for (int j = 0; j < 8; j++) bb[j] = __ldg(&b1[bn * 128 + tx * 8 + j]);

    float acc[8][8];
#pragma unroll
    for (int i = 0; i < 8; i++)
#pragma unroll
        for (int j = 0; j < 8; j++) acc[i][j] = 0.f;

    for (int k0 = 0; k0 < D_IN; k0 += 8) {
        float4 av = *(const float4*)(xrow + k0 + acol);
        float4 bv = *(const float4*)(W1 + (size_t)(k0 + brow) * D_H + bn * 128 + bcol);
        As[acol + 0][arow] = av.x;
        As[acol + 1][arow] = av.y;
        As[acol + 2][arow] = av.z;
        As[acol + 3][arow] = av.w;
        *(float4*)&Bs[brow][bcol] = bv;
        __syncthreads();

#pragma unroll
        for (int kk = 0; kk < 8; kk++) {
            float4 a0 = *(const float4*)&As[kk][ty * 8];
            float4 a1 = *(const float4*)&As[kk][ty * 8 + 4];
            float4 b0 = *(const float4*)&Bs[kk][tx * 8];
            float4 b1v = *(const float4*)&Bs[kk][tx * 8 + 4];
            float a[8] = {a0.x, a0.y, a0.z, a0.w, a1.x, a1.y, a1.z, a1.w};
            float b[8] = {b0.x, b0.y, b0.z, b0.w, b1v.x, b1v.y, b1v.z, b1v.w};
#pragma unroll
            for (int i = 0; i < 8; i++)
#pragma unroll
                for (int j = 0; j < 8; j++) acc[i][j] = fmaf(a[i], b[j], acc[i][j]);
        }
        __syncthreads();
    }

    // epilogue: bias + relu, store to sorted h
#pragma unroll
    for (int i = 0; i < 8; i++) {
        int p = p0 + ty * 8 + i;
        float* hrow = g_h + (size_t)p * D_H + bn * 128 + tx * 8;
#pragma unroll
        for (int j = 0; j < 8; j += 4) {
            float4 v;
            v.x = fmaxf(acc[i][j + 0] + bb[j + 0], 0.f);
            v.y = fmaxf(acc[i][j + 1] + bb[j + 1], 0.f);
            v.z = fmaxf(acc[i][j + 2] + bb[j + 2], 0.f);
            v.w = fmaxf(acc[i][j + 3] + bb[j + 3], 0.f);
            *(float4*)(hrow + j) = v;
        }
    }
}

// ---------------- GEMM2: out[orig] = sigmoid(h_sorted @ We[e] + be[e]) ----------------
__global__ __launch_bounds__(256) void gemm2(const float* __restrict__ We,
                                             const float* __restrict__ be,
                                             float* __restrict__ out) {
    __shared__ float As[8][TILE_M];
    __shared__ float Bs[8][128];
    __shared__ int   s_start[N_EXP + 1];

    const int tid = threadIdx.x;
    if (tid <= N_EXP) s_start[tid] = g_start[tid];
    __syncthreads();

    const int p0 = blockIdx.x * TILE_M;
    if (p0 >= s_start[N_EXP]) return;    // padding-only region beyond actual total

    // find expert owning this tile (tiles never span experts: segments are 128-padded)
    int e = 0;
    while (e < N_EXP - 1 && s_start[e + 1] <= p0) e++;
    const int valid_end = s_start[e] + g_counts[e];

    const int ty = tid >> 4;
    const int tx = tid & 15;
    const int arow = tid >> 1;
    const int acol = (tid & 1) * 4;
    const int brow = tid >> 5;
    const int bcol = (tid & 31) * 4;

    const float* A  = g_h + (size_t)(p0 + arow) * D_H;
    const float* Bm = We + (size_t)e * D_H * D_OUT;

    float bb[8];
#pragma unroll
    for (int j = 0; j < 8; j++) bb[j] = __ldg(&be[e * D_OUT + tx * 8 + j]);

    float acc[8][8];
#pragma unroll
    for (int i = 0; i < 8; i++)
#pragma unroll
        for (int j = 0; j < 8; j++) acc[i][j] = 0.f;

    for (int k0 = 0; k0 < D_H; k0 += 8) {
        float4 av = *(const float4*)(A + k0 + acol);
        float4 bv = *(const float4*)(Bm + (size_t)(k0 + brow) * D_OUT + bcol);
        As[acol + 0][arow] = av.x;
        As[acol + 1][arow] = av.y;
        As[acol + 2][arow] = av.z;
        As[acol + 3][arow] = av.w;
        *(float4*)&Bs[brow][bcol] = bv;
        __syncthreads();

#pragma unroll
        for (int kk = 0; kk < 8; kk++) {
            float4 a0 = *(const float4*)&As[kk][ty * 8];
            float4 a1 = *(const float4*)&As[kk][ty * 8 + 4];
            float4 b0 = *(const float4*)&Bs[kk][tx * 8];
            float4 b1v = *(const float4*)&Bs[kk][tx * 8 + 4];
            float a[8] = {a0.x, a0.y, a0.z, a0.w, a1.x, a1.y, a1.z, a1.w};
            float b[8] = {b0.x, b0.y, b0.z, b0.w, b1v.x, b1v.y, b1v.z, b1v.w};
#pragma unroll
            for (int i = 0; i < 8; i++)
#pragma unroll
                for (int j = 0; j < 8; j++) acc[i][j] = fmaf(a[i], b[j], acc[i][j]);
        }
        __syncthreads();
    }

    // epilogue: bias + sigmoid, scatter to original rows (valid rows only)
#pragma unroll
    for (int i = 0; i < 8; i++) {
        int p = p0 + ty * 8 + i;
        if (p < valid_end) {
            int orow = g_sorted[p];
            float* orow_ptr = out + (size_t)orow * D_OUT + tx * 8;
#pragma unroll
            for (int j = 0; j < 8; j += 4) {
                float4 v;
                v.x = 1.f / (1.f + expf(-(acc[i][j + 0] + bb[j + 0])));
                v.y = 1.f / (1.f + expf(-(acc[i][j + 1] + bb[j + 1])));
                v.z = 1.f / (1.f + expf(-(acc[i][j + 2] + bb[j + 2])));
                v.w = 1.f / (1.f + expf(-(acc[i][j + 3] + bb[j + 3])));
                *(float4*)(orow_ptr + j) = v;
            }
        }
    }
}

// ---------------- launch ----------------
extern "C" void kernel_launch(void* const* d_in, const int* in_sizes, int n_in,
                              void* d_out, int out_size) {
    // metadata order: x, num, c, W1, b1, We, be
    const float* x   = (const float*)d_in[0];
    const int*   num = (const int*)d_in[1];
    const int*   c   = (const int*)d_in[2];
    const float* W1  = (const float*)d_in[3];
    const float* b1  = (const float*)d_in[4];
    const float* We  = (const float*)d_in[5];
    const float* be  = (const float*)d_in[6];
    float* out = (float*)d_out;

    r0_zero<<<1, 32>>>();
    r1_count<<<B / 256, 256>>>(num, c);
    r2_scan<<<1, 1>>>();
    r3_scatter<<<B / 256, 256>>>(num, c);

    dim3 g1(D_H / 128, MT1);   // (4, 528): consecutive blocks share the same x row-tile via L2
    gemm1<<<g1, 256>>>(x, W1, b1);
    gemm2<<<MT1, 256>>>(We, be, out);
}

// round 3
// speedup vs baseline: 2.7479x; 2.7479x over previous
#include <cuda_runtime.h>
#include <cstdint>
#include <math.h>

// ---------------- problem constants ----------------
#define B_ROWS 65536
#define D_IN   512
#define D_H    512
#define D_OUT  128
#define N_EXP  16
#define TILE_M 128
#define MAXP   (B_ROWS + N_EXP * TILE_M)   // 67584
#define MT1    (MAXP / TILE_M)             // 528

#define PAD 36                              // floats per smem row (conflict-free + 16B aligned)
#define STG_BYTES   (128 * PAD * 4)         // 18432 per operand tile
#define STAGE_BYTES (2 * STG_BYTES)         // 36864 per stage (A+B)
#define DSMEM_BYTES (2 * STAGE_BYTES)       // 73728, double buffered

// ---------------- device scratch ----------------
__device__ float g_xr[(size_t)B_ROWS * D_IN];         // x rounded to tf32 (rna)
__device__ float g_h[(size_t)MAXP * D_H];             // sorted hidden acts (tf32-rounded)
__device__ float g_w1t[(size_t)D_H * D_IN];           // W1^T [n][k], tf32-rounded
__device__ float g_wet[(size_t)N_EXP * D_OUT * D_H];  // We^T [e][o][k], tf32-rounded
__device__ int   g_counts[N_EXP];
__device__ int   g_cursor[N_EXP];
__device__ int   g_start[N_EXP + 1];
__device__ int   g_sorted[MAXP];

// ---------------- helpers ----------------
__device__ __forceinline__ uint32_t smem_u32(const void* p) {
    uint32_t a;
    asm("{ .reg .u64 t; cvta.to.shared.u64 t, %1; cvt.u32.u64 %0, t; }" : "=r"(a) : "l"(p));
    return a;
}
__device__ __forceinline__ float to_tf32(float f) {
    float o;
    asm("cvt.rna.tf32.f32 %0, %1;" : "=f"(o) : "f"(f));
    return o;
}
__device__ __forceinline__ void cp16(uint32_t dst, const void* src) {
    asm volatile("cp.async.cg.shared.global [%0], [%1], 16;" :: "r"(dst), "l"(src));
}
#define CP_COMMIT()  asm volatile("cp.async.commit_group;")
#define CP_WAIT_1()  asm volatile("cp.async.wait_group 1;")
#define CP_WAIT_0()  asm volatile("cp.async.wait_group 0;")

__device__ __forceinline__ void mma8(float* c, const uint32_t* a, const uint32_t* b) {
    asm volatile(
        "mma.sync.aligned.m16n8k8.row.col.f32.tf32.tf32.f32 "
        "{%0,%1,%2,%3}, {%4,%5,%6,%7}, {%8,%9}, {%0,%1,%2,%3};"
        : "+f"(c[0]), "+f"(c[1]), "+f"(c[2]), "+f"(c[3])
        : "r"(a[0]), "r"(a[1]), "r"(a[2]), "r"(a[3]), "r"(b[0]), "r"(b[1]));
}

// ---------------- routing ----------------
__global__ void r0_zero() {
    int t = threadIdx.x;
    if (t < N_EXP) { g_counts[t] = 0; g_cursor[t] = 0; }
}
__global__ void r1_count(const int* __restrict__ num, const int* __restrict__ c) {
    __shared__ int h[N_EXP];
    int tid = threadIdx.x;
    if (tid < N_EXP) h[tid] = 0;
    __syncthreads();
    int i = blockIdx.x * blockDim.x + tid;
    if (i < B_ROWS) atomicAdd(&h[c[num[i]]], 1);
    __syncthreads();
    if (tid < N_EXP && h[tid]) atomicAdd(&g_counts[tid], h[tid]);
}
__global__ void r2_scan() {
    int s = 0;
    g_start[0] = 0;
    for (int e = 0; e < N_EXP; e++) {
        s += (g_counts[e] + TILE_M - 1) & ~(TILE_M - 1);
        g_start[e + 1] = s;
    }
}
__global__ void r3_scatter(const int* __restrict__ num, const int* __restrict__ c) {
    int i = blockIdx.x * blockDim.x + threadIdx.x;
    if (i >= B_ROWS) return;
    int e = c[num[i]];
    unsigned lane = threadIdx.x & 31;
    unsigned mask = __match_any_sync(0xffffffffu, e);
    int leader = __ffs(mask) - 1;
    int rank = __popc(mask & ((1u << lane) - 1u));
    int base = 0;
    if ((int)lane == leader) base = atomicAdd(&g_cursor[e], __popc(mask));
    base = __shfl_sync(0xffffffffu, base, leader);
    g_sorted[g_start[e] + base + rank] = i;
}

// ---------------- pre-round x to tf32 ----------------
__global__ void round_x(const float* __restrict__ x) {
    size_t i = ((size_t)blockIdx.x * 256 + threadIdx.x) * 4;
    float4 v = *(const float4*)(x + i);
    float4 t;
    t.x = to_tf32(v.x); t.y = to_tf32(v.y); t.z = to_tf32(v.z); t.w = to_tf32(v.w);
    *(float4*)(g_xr + i) = t;
}

// ---------------- weight transposes (tf32-rounded) ----------------
__global__ void tr_w1(const float* __restrict__ W1) {
    __shared__ float t[32][33];
    int x0 = blockIdx.x * 32;   // n
    int y0 = blockIdx.y * 32;   // k
    for (int i = threadIdx.y; i < 32; i += 8)
        t[i][threadIdx.x] = W1[(size_t)(y0 + i) * D_H + x0 + threadIdx.x];
    __syncthreads();
    for (int i = threadIdx.y; i < 32; i += 8)
        g_w1t[(size_t)(x0 + i) * D_IN + y0 + threadIdx.x] = to_tf32(t[threadIdx.x][i]);
}
__global__ void tr_we(const float* __restrict__ We) {
    __shared__ float t[32][33];
    int e = blockIdx.z;
    int x0 = blockIdx.x * 32;   // o
    int y0 = blockIdx.y * 32;   // k
    const float* src = We + (size_t)e * D_H * D_OUT;
    for (int i = threadIdx.y; i < 32; i += 8)
        t[i][threadIdx.x] = src[(size_t)(y0 + i) * D_OUT + x0 + threadIdx.x];
    __syncthreads();
    float* dst = g_wet + (size_t)e * D_OUT * D_H;
    for (int i = threadIdx.y; i < 32; i += 8)
        dst[(size_t)(x0 + i) * D_H + y0 + threadIdx.x] = to_tf32(t[threadIdx.x][i]);
}

// ---------------- GEMM1: h = relu(x[sorted] @ W1 + b1), tf32 mma.sync ----------------
// grid (4 col tiles, 528 row tiles), 256 threads, BM=BN=128, BK=32, double buffer
__global__ __launch_bounds__(256, 2) void gemm1(const float* __restrict__ b1) {
    extern __shared__ char dsm[];
    __shared__ int   rows_s[128];
    __shared__ float bias_s[128];

    const int tid = threadIdx.x, lane = tid & 31, wid = tid >> 5;
    const int bn = blockIdx.x;
    const int p0 = blockIdx.y * TILE_M;

    if (tid < 128) {
        int r = g_sorted[p0 + tid];
        rows_s[tid] = min(max(r, 0), B_ROWS - 1);
        bias_s[tid] = b1[bn * 128 + tid];
    }
    __syncthreads();

    const uint32_t sb = smem_u32(dsm);

    // per-thread cp.async chunks: 4 for A, 4 for B (1024 16B chunks each / 256 thr)
    const float* asrc[4];
    const float* bsrc[4];
    uint32_t adst[4], bdst[4];
#pragma unroll
    for (int i = 0; i < 4; i++) {
        int id = tid + i * 256;
        int r = id >> 3, q = id & 7;
        asrc[i] = g_xr + (size_t)rows_s[r] * D_IN + q * 4;
        bsrc[i] = g_w1t + (size_t)(bn * 128 + r) * D_IN + q * 4;
        adst[i] = sb + (uint32_t)(r * PAD * 4 + q * 16);
        bdst[i] = adst[i] + STG_BYTES;
    }

    // stage 0
#pragma unroll
    for (int i = 0; i < 4; i++) { cp16(adst[i], asrc[i]); cp16(bdst[i], bsrc[i]); }
    CP_COMMIT();

    float acc[4][4][4];
#pragma unroll
    for (int mt = 0; mt < 4; mt++)
#pragma unroll
        for (int nt = 0; nt < 4; nt++)
#pragma unroll
            for (int k = 0; k < 4; k++) acc[mt][nt][k] = 0.f;

    const int wm = wid >> 2, wn = wid & 3;
    const int lr = lane >> 2, lc = lane & 3;

    for (int s = 0; s < 16; s++) {
        if (s + 1 < 16) {
            uint32_t off = (uint32_t)(((s + 1) & 1) * STAGE_BYTES);
            int ksrc = (s + 1) * 32;
#pragma unroll
            for (int i = 0; i < 4; i++) {
                cp16(adst[i] + off, asrc[i] + ksrc);
                cp16(bdst[i] + off, bsrc[i] + ksrc);
            }
            CP_COMMIT();
            CP_WAIT_1();
        } else {
            CP_WAIT_0();
        }
        __syncthreads();

        const uint32_t* As = (const uint32_t*)(dsm + (s & 1) * STAGE_BYTES);
        const uint32_t* Bs = (const uint32_t*)(dsm + (s & 1) * STAGE_BYTES + STG_BYTES);
#pragma unroll
        for (int ks = 0; ks < 4; ks++) {
            const int k0 = ks * 8;
            uint32_t a[4][4], b[4][2];
#pragma unroll
            for (int mt = 0; mt < 4; mt++) {
                int row = wm * 64 + mt * 16 + lr;
                a[mt][0] = As[row * PAD + k0 + lc];
                a[mt][1] = As[(row + 8) * PAD + k0 + lc];
                a[mt][2] = As[row * PAD + k0 + lc + 4];
                a[mt][3] = As[(row + 8) * PAD + k0 + lc + 4];
            }
#pragma unroll
            for (int nt = 0; nt < 4; nt++) {
                int col = wn * 32 + nt * 8 + lr;
                b[nt][0] = Bs[col * PAD + k0 + lc];
                b[nt][1] = Bs[col * PAD + k0 + lc + 4];
            }
#pragma unroll
            for (int mt = 0; mt < 4; mt++)
#pragma unroll
                for (int nt = 0; nt < 4; nt++)
                    mma8(acc[mt][nt], a[mt], b[nt]);
        }
        __syncthreads();
    }

    // epilogue: bias + relu + tf32-round, write sorted h
#pragma unroll
    for (int mt = 0; mt < 4; mt++) {
        int m = wm * 64 + mt * 16 + lr;
#pragma unroll
        for (int nt = 0; nt < 4; nt++) {
            int n = wn * 32 + nt * 8 + lc * 2;
            float bi0 = bias_s[n], bi1 = bias_s[n + 1];
            float2 v0, v1;
            v0.x = to_tf32(fmaxf(acc[mt][nt][0] + bi0, 0.f));
            v0.y = to_tf32(fmaxf(acc[mt][nt][1] + bi1, 0.f));
            v1.x = to_tf32(fmaxf(acc[mt][nt][2] + bi0, 0.f));
            v1.y = to_tf32(fmaxf(acc[mt][nt][3] + bi1, 0.f));
            *(float2*)(g_h + (size_t)(p0 + m) * D_H + bn * 128 + n) = v0;
            *(float2*)(g_h + (size_t)(p0 + m + 8) * D_H + bn * 128 + n) = v1;
        }
    }
}

// ---------------- GEMM2: out[orig] = sigmoid(h @ We[e]^T + be[e]) ----------------
__global__ __launch_bounds__(256, 2) void gemm2(const float* __restrict__ be,
                                                float* __restrict__ out) {
    const int p0 = blockIdx.x * TILE_M;
    if (p0 >= g_start[N_EXP]) return;

    extern __shared__ char dsm[];
    __shared__ int   rows_s[128];
    __shared__ float bias_s[128];

    int e = 0;
    while (e < N_EXP - 1 && g_start[e + 1] <= p0) e++;
    const int valid_end = g_start[e] + g_counts[e];

    const int tid = threadIdx.x, lane = tid & 31, wid = tid >> 5;
    if (tid < 128) {
        rows_s[tid] = g_sorted[p0 + tid];
        bias_s[tid] = be[e * D_OUT + tid];
    }
    __syncthreads();

    const uint32_t sb = smem_u32(dsm);
    const float* Asrc = g_h + (size_t)p0 * D_H;
    const float* Bsrc = g_wet + (size_t)e * D_OUT * D_H;

    const float* asrc[4];
    const float* bsrc[4];
    uint32_t adst[4], bdst[4];
#pragma unroll
    for (int i = 0; i < 4; i++) {
        int id = tid + i * 256;
        int r = id >> 3, q = id & 7;
        asrc[i] = Asrc + (size_t)r * D_H + q * 4;
        bsrc[i] = Bsrc + (size_t)r * D_H + q * 4;
        adst[i] = sb + (uint32_t)(r * PAD * 4 + q * 16);
        bdst[i] = adst[i] + STG_BYTES;
    }

#pragma unroll
    for (int i = 0; i < 4; i++) { cp16(adst[i], asrc[i]); cp16(bdst[i], bsrc[i]); }
    CP_COMMIT();

    float acc[4][4][4];
#pragma unroll
    for (int mt = 0; mt < 4; mt++)
#pragma unroll
        for (int nt = 0; nt < 4; nt++)
#pragma unroll
            for (int k = 0; k < 4; k++) acc[mt][nt][k] = 0.f;

    const int wm = wid >> 2, wn = wid & 3;
    const int lr = lane >> 2, lc = lane & 3;

    for (int s = 0; s < 16; s++) {
        if (s + 1 < 16) {
            uint32_t off = (uint32_t)(((s + 1) & 1) * STAGE_BYTES);
            int ksrc = (s + 1) * 32;
#pragma unroll
            for (int i = 0; i < 4; i++) {
                cp16(adst[i] + off, asrc[i] + ksrc);
                cp16(bdst[i] + off, bsrc[i] + ksrc);
            }
            CP_COMMIT();
            CP_WAIT_1();
        } else {
            CP_WAIT_0();
        }
        __syncthreads();

        const uint32_t* As = (const uint32_t*)(dsm + (s & 1) * STAGE_BYTES);
        const uint32_t* Bs = (const uint32_t*)(dsm + (s & 1) * STAGE_BYTES + STG_BYTES);
#pragma unroll
        for (int ks = 0; ks < 4; ks++) {
            const int k0 = ks * 8;
            uint32_t a[4][4], b[4][2];
#pragma unroll
            for (int mt = 0; mt < 4; mt++) {
                int row = wm * 64 + mt * 16 + lr;
                a[mt][0] = As[row * PAD + k0 + lc];
                a[mt][1] = As[(row + 8) * PAD + k0 + lc];
                a[mt][2] = As[row * PAD + k0 + lc + 4];
                a[mt][3] = As[(row + 8) * PAD + k0 + lc + 4];
            }
#pragma unroll
            for (int nt = 0; nt < 4; nt++) {
                int col = wn * 32 + nt * 8 + lr;
                b[nt][0] = Bs[col * PAD + k0 + lc];
                b[nt][1] = Bs[col * PAD + k0 + lc + 4];
            }
#pragma unroll
            for (int mt = 0; mt < 4; mt++)
#pragma unroll
                for (int nt = 0; nt < 4; nt++)
                    mma8(acc[mt][nt], a[mt], b[nt]);
        }
        __syncthreads();
    }

    // epilogue: bias + sigmoid, scatter valid rows
#pragma unroll
    for (int mt = 0; mt < 4; mt++) {
        int m = wm * 64 + mt * 16 + lr;
#pragma unroll
        for (int nt = 0; nt < 4; nt++) {
            int n = wn * 32 + nt * 8 + lc * 2;
            float bi0 = bias_s[n], bi1 = bias_s[n + 1];
            if (p0 + m < valid_end) {
                float2 v;
                v.x = 1.f / (1.f + __expf(-(acc[mt][nt][0] + bi0)));
                v.y = 1.f / (1.f + __expf(-(acc[mt][nt][1] + bi1)));
                *(float2*)(out + (size_t)rows_s[m] * D_OUT + n) = v;
            }
            if (p0 + m + 8 < valid_end) {
                float2 v;
                v.x = 1.f / (1.f + __expf(-(acc[mt][nt][2] + bi0)));
                v.y = 1.f / (1.f + __expf(-(acc[mt][nt][3] + bi1)));
                *(float2*)(out + (size_t)rows_s[m + 8] * D_OUT + n) = v;
            }
        }
    }
}

// ---------------- launch ----------------
extern "C" void kernel_launch(void* const* d_in, const int* in_sizes, int n_in,
                              void* d_out, int out_size) {
    const float* x   = (const float*)d_in[0];
    const int*   num = (const int*)d_in[1];
    const int*   c   = (const int*)d_in[2];
    const float* W1  = (const float*)d_in[3];
    const float* b1  = (const float*)d_in[4];
    const float* We  = (const float*)d_in[5];
    const float* be  = (const float*)d_in[6];
    float* out = (float*)d_out;

    static bool attr_done = false;
    if (!attr_done) {
        cudaFuncSetAttribute(gemm1, cudaFuncAttributeMaxDynamicSharedMemorySize, DSMEM_BYTES);
        cudaFuncSetAttribute(gemm2, cudaFuncAttributeMaxDynamicSharedMemorySize, DSMEM_BYTES);
        attr_done = true;
    }

    round_x<<<(B_ROWS * D_IN) / (256 * 4), 256>>>(x);

    dim3 tb(32, 8);
    tr_w1<<<dim3(16, 16), tb>>>(W1);
    tr_we<<<dim3(4, 16, 16), tb>>>(We);

    r0_zero<<<1, 32>>>();
    r1_count<<<B_ROWS / 256, 256>>>(num, c);
    r2_scan<<<1, 1>>>();
    r3_scatter<<<B_ROWS / 256, 256>>>(num, c);

    gemm1<<<dim3(4, MT1), 256, DSMEM_BYTES>>>(b1);
    gemm2<<<MT1, 256, DSMEM_BYTES>>>(be, out);
}

// round 4
// speedup vs baseline: 4.3523x; 1.5839x over previous
#include <cuda_runtime.h>
#include <cuda_fp16.h>
#include <cstdint>
#include <math.h>

// ---------------- problem constants ----------------
#define B_ROWS 65536
#define D_IN   512
#define D_H    512
#define D_OUT  128
#define N_EXP  16
#define TILE_M 128
#define MAXP   (B_ROWS + N_EXP * TILE_M)   // 67584
#define MT1    (MAXP / TILE_M)             // 528

#define PAD_H 40                            // halves per smem row (80 B, conflict-free)
#define STG_BYTES   (128 * PAD_H * 2)       // 10240 per operand tile
#define STAGE_BYTES (2 * STG_BYTES)         // 20480 per stage (A+B)
#define NSTAGE 4
#define DSMEM_BYTES (NSTAGE * STAGE_BYTES)  // 81920

// ---------------- device scratch ----------------
__device__ __half g_xh[(size_t)B_ROWS * D_IN];          // x in fp16
__device__ __half g_h[(size_t)MAXP * D_H];              // sorted hidden acts, fp16
__device__ __half g_w1t[(size_t)D_H * D_IN];            // W1^T [n][k], fp16
__device__ __half g_wet[(size_t)N_EXP * D_OUT * D_H];   // We^T [e][o][k], fp16
__device__ int   g_counts[N_EXP];
__device__ int   g_cursor[N_EXP];
__device__ int   g_start[N_EXP + 1];
__device__ int   g_sorted[MAXP];

// ---------------- helpers ----------------
__device__ __forceinline__ uint32_t smem_u32(const void* p) {
    uint32_t a;
    asm("{ .reg .u64 t; cvta.to.shared.u64 t, %1; cvt.u32.u64 %0, t; }" : "=r"(a) : "l"(p));
    return a;
}
__device__ __forceinline__ void cp16(uint32_t dst, const void* src) {
    asm volatile("cp.async.cg.shared.global [%0], [%1], 16;" :: "r"(dst), "l"(src));
}
#define CP_COMMIT()  asm volatile("cp.async.commit_group;")
#define CP_WAIT_2()  asm volatile("cp.async.wait_group 2;")

__device__ __forceinline__ void mma16(float* c, const uint32_t* a, const uint32_t* b) {
    asm volatile(
        "mma.sync.aligned.m16n8k16.row.col.f32.f16.f16.f32 "
        "{%0,%1,%2,%3}, {%4,%5,%6,%7}, {%8,%9}, {%0,%1,%2,%3};"
        : "+f"(c[0]), "+f"(c[1]), "+f"(c[2]), "+f"(c[3])
        : "r"(a[0]), "r"(a[1]), "r"(a[2]), "r"(a[3]), "r"(b[0]), "r"(b[1]));
}

// ---------------- cvt x -> fp16 (+ zero routing counters) ----------------
__global__ void cvt_x(const float* __restrict__ x) {
    if (blockIdx.x == 0 && threadIdx.x < N_EXP) {
        g_counts[threadIdx.x] = 0;
        g_cursor[threadIdx.x] = 0;
    }
    size_t i = ((size_t)blockIdx.x * 256 + threadIdx.x) * 8;
    float4 v0 = *(const float4*)(x + i);
    float4 v1 = *(const float4*)(x + i + 4);
    __half2 h[4];
    h[0] = __floats2half2_rn(v0.x, v0.y);
    h[1] = __floats2half2_rn(v0.z, v0.w);
    h[2] = __floats2half2_rn(v1.x, v1.y);
    h[3] = __floats2half2_rn(v1.z, v1.w);
    *(uint4*)(g_xh + i) = *(uint4*)h;
}

// ---------------- routing ----------------
__global__ void r1_count(const int* __restrict__ num, const int* __restrict__ c) {
    __shared__ int h[N_EXP];
    int tid = threadIdx.x;
    if (tid < N_EXP) h[tid] = 0;
    __syncthreads();
    int i = blockIdx.x * blockDim.x + tid;
    if (i < B_ROWS) atomicAdd(&h[c[num[i]]], 1);
    __syncthreads();
    if (tid < N_EXP && h[tid]) atomicAdd(&g_counts[tid], h[tid]);
}
__global__ void r2_scan() {
    int s = 0;
    g_start[0] = 0;
    for (int e = 0; e < N_EXP; e++) {
        s += (g_counts[e] + TILE_M - 1) & ~(TILE_M - 1);
        g_start[e + 1] = s;
    }
}
__global__ void r3_scatter(const int* __restrict__ num, const int* __restrict__ c) {
    int i = blockIdx.x * blockDim.x + threadIdx.x;
    if (i >= B_ROWS) return;
    int e = c[num[i]];
    unsigned lane = threadIdx.x & 31;
    unsigned mask = __match_any_sync(0xffffffffu, e);
    int leader = __ffs(mask) - 1;
    int rank = __popc(mask & ((1u << lane) - 1u));
    int base = 0;
    if ((int)lane == leader) base = atomicAdd(&g_cursor[e], __popc(mask));
    base = __shfl_sync(0xffffffffu, base, leader);
    g_sorted[g_start[e] + base + rank] = i;
}

// ---------------- weight transposes (fp16) ----------------
__global__ void tr_w1(const float* __restrict__ W1) {
    __shared__ float t[32][33];
    int x0 = blockIdx.x * 32;   // n
    int y0 = blockIdx.y * 32;   // k
    for (int i = threadIdx.y; i < 32; i += 8)
        t[i][threadIdx.x] = W1[(size_t)(y0 + i) * D_H + x0 + threadIdx.x];
    __syncthreads();
    for (int i = threadIdx.y; i < 32; i += 8)
        g_w1t[(size_t)(x0 + i) * D_IN + y0 + threadIdx.x] = __float2half_rn(t[threadIdx.x][i]);
}
__global__ void tr_we(const float* __restrict__ We) {
    __shared__ float t[32][33];
    int e = blockIdx.z;
    int x0 = blockIdx.x * 32;   // o
    int y0 = blockIdx.y * 32;   // k
    const float* src = We + (size_t)e * D_H * D_OUT;
    for (int i = threadIdx.y; i < 32; i += 8)
        t[i][threadIdx.x] = src[(size_t)(y0 + i) * D_OUT + x0 + threadIdx.x];
    __syncthreads();
    __half* dst = g_wet + (size_t)e * D_OUT * D_H;
    for (int i = threadIdx.y; i < 32; i += 8)
        dst[(size_t)(x0 + i) * D_H + y0 + threadIdx.x] = __float2half_rn(t[threadIdx.x][i]);
}

// ================= GEMM cores (fp16 mma.sync, 4-stage cp.async) =================
// 256 threads, BM=BN=128, BK=32; warps 2x4; warp tile 64x32; 4x4 m16n8k16

// ---------------- GEMM1: h = relu(x[sorted] @ W1 + b1) ----------------
__global__ __launch_bounds__(256, 2) void gemm1(const float* __restrict__ b1) {
    const int p0 = blockIdx.y * TILE_M;
    if (p0 >= g_start[N_EXP]) return;

    extern __shared__ char dsm[];
    __shared__ int   rows_s[128];
    __shared__ float bias_s[128];

    const int tid = threadIdx.x, lane = tid & 31, wid = tid >> 5;
    const int bn = blockIdx.x;

    if (tid < 128) {
        int r = g_sorted[p0 + tid];
        rows_s[tid] = min(max(r, 0), B_ROWS - 1);
        bias_s[tid] = b1[bn * 128 + tid];
    }
    __syncthreads();

    const uint32_t sb = smem_u32(dsm);

    // per-thread cp.async chunks: 2 for A, 2 for B (512 chunks each / 256 thr)
    const __half* asrc[2];
    const __half* bsrc[2];
    uint32_t adst[2], bdst[2];
#pragma unroll
    for (int i = 0; i < 2; i++) {
        int id = tid + i * 256;
        int r = id >> 2, q = id & 3;
        asrc[i] = g_xh + (size_t)rows_s[r] * D_IN + q * 8;
        bsrc[i] = g_w1t + (size_t)(bn * 128 + r) * D_IN + q * 8;
        adst[i] = sb + (uint32_t)(r * (PAD_H * 2) + q * 16);
        bdst[i] = adst[i] + STG_BYTES;
    }

    // prefetch stages 0..2
#pragma unroll
    for (int s = 0; s < 3; s++) {
        uint32_t off = (uint32_t)(s * STAGE_BYTES);
        int k = s * 32;
#pragma unroll
        for (int i = 0; i < 2; i++) {
            cp16(adst[i] + off, asrc[i] + k);
            cp16(bdst[i] + off, bsrc[i] + k);
        }
        CP_COMMIT();
    }

    float acc[4][4][4];
#pragma unroll
    for (int mt = 0; mt < 4; mt++)
#pragma unroll
        for (int nt = 0; nt < 4; nt++)
#pragma unroll
            for (int k = 0; k < 4; k++) acc[mt][nt][k] = 0.f;

    const int wm = wid >> 2, wn = wid & 3;
    const int lr = lane >> 2, lc = lane & 3;

    for (int s = 0; s < 16; s++) {
        CP_WAIT_2();
        __syncthreads();
        if (s + 3 < 16) {
            uint32_t off = (uint32_t)(((s + 3) & (NSTAGE - 1)) * STAGE_BYTES);
            int k = (s + 3) * 32;
#pragma unroll
            for (int i = 0; i < 2; i++) {
                cp16(adst[i] + off, asrc[i] + k);
                cp16(bdst[i] + off, bsrc[i] + k);
            }
        }
        CP_COMMIT();

        const uint32_t* As = (const uint32_t*)(dsm + (s & (NSTAGE - 1)) * STAGE_BYTES);
        const uint32_t* Bs = (const uint32_t*)(dsm + (s & (NSTAGE - 1)) * STAGE_BYTES + STG_BYTES);
#pragma unroll
        for (int ks = 0; ks < 2; ks++) {
            const int kq = ks * 8;  // k0/2
            uint32_t a[4][4], b[4][2];
#pragma unroll
            for (int mt = 0; mt < 4; mt++) {
                int row = wm * 64 + mt * 16 + lr;
                a[mt][0] = As[row * (PAD_H / 2) + kq + lc];
                a[mt][1] = As[(row + 8) * (PAD_H / 2) + kq + lc];
                a[mt][2] = As[row * (PAD_H / 2) + kq + lc + 4];
                a[mt][3] = As[(row + 8) * (PAD_H / 2) + kq + lc + 4];
            }
#pragma unroll
            for (int nt = 0; nt < 4; nt++) {
                int col = wn * 32 + nt * 8 + lr;
                b[nt][0] = Bs[col * (PAD_H / 2) + kq + lc];
                b[nt][1] = Bs[col * (PAD_H / 2) + kq + lc + 4];
            }
#pragma unroll
            for (int mt = 0; mt < 4; mt++)
#pragma unroll
                for (int nt = 0; nt < 4; nt++)
                    mma16(acc[mt][nt], a[mt], b[nt]);
        }
    }

    // epilogue: bias + relu, write sorted h as fp16
#pragma unroll
    for (int mt = 0; mt < 4; mt++) {
        int m = wm * 64 + mt * 16 + lr;
#pragma unroll
        for (int nt = 0; nt < 4; nt++) {
            int n = wn * 32 + nt * 8 + lc * 2;
            float bi0 = bias_s[n], bi1 = bias_s[n + 1];
            __half2 v0 = __floats2half2_rn(fmaxf(acc[mt][nt][0] + bi0, 0.f),
                                           fmaxf(acc[mt][nt][1] + bi1, 0.f));
            __half2 v1 = __floats2half2_rn(fmaxf(acc[mt][nt][2] + bi0, 0.f),
                                           fmaxf(acc[mt][nt][3] + bi1, 0.f));
            *(__half2*)(g_h + (size_t)(p0 + m) * D_H + bn * 128 + n) = v0;
            *(__half2*)(g_h + (size_t)(p0 + m + 8) * D_H + bn * 128 + n) = v1;
        }
    }
}

// ---------------- GEMM2: out[orig] = sigmoid(h @ We[e]^T + be[e]) ----------------
__global__ __launch_bounds__(256, 2) void gemm2(const float* __restrict__ be,
                                                float* __restrict__ out) {
    const int p0 = blockIdx.x * TILE_M;
    if (p0 >= g_start[N_EXP]) return;

    extern __shared__ char dsm[];
    __shared__ int   rows_s[128];
    __shared__ float bias_s[128];

    int e = 0;
    while (e < N_EXP - 1 && g_start[e + 1] <= p0) e++;
    const int valid_end = g_start[e] + g_counts[e];

    const int tid = threadIdx.x, lane = tid & 31, wid = tid >> 5;
    if (tid < 128) {
        rows_s[tid] = g_sorted[p0 + tid];
        bias_s[tid] = be[e * D_OUT + tid];
    }
    __syncthreads();

    const uint32_t sb = smem_u32(dsm);
    const __half* Ab = g_h + (size_t)p0 * D_H;
    const __half* Bb = g_wet + (size_t)e * D_OUT * D_H;

    const __half* asrc[2];
    const __half* bsrc[2];
    uint32_t adst[2], bdst[2];
#pragma unroll
    for (int i = 0; i < 2; i++) {
        int id = tid + i * 256;
        int r = id >> 2, q = id & 3;
        asrc[i] = Ab + (size_t)r * D_H + q * 8;
        bsrc[i] = Bb + (size_t)r * D_H + q * 8;
        adst[i] = sb + (uint32_t)(r * (PAD_H * 2) + q * 16);
        bdst[i] = adst[i] + STG_BYTES;
    }

#pragma unroll
    for (int s = 0; s < 3; s++) {
        uint32_t off = (uint32_t)(s * STAGE_BYTES);
        int k = s * 32;
#pragma unroll
        for (int i = 0; i < 2; i++) {
            cp16(adst[i] + off, asrc[i] + k);
            cp16(bdst[i] + off, bsrc[i] + k);
        }
        CP_COMMIT();
    }

    float acc[4][4][4];
#pragma unroll
    for (int mt = 0; mt < 4; mt++)
#pragma unroll
        for (int nt = 0; nt < 4; nt++)
#pragma unroll
            for (int k = 0; k < 4; k++) acc[mt][nt][k] = 0.f;

    const int wm = wid >> 2, wn = wid & 3;
    const int lr = lane >> 2, lc = lane & 3;

    for (int s = 0; s < 16; s++) {
        CP_WAIT_2();
        __syncthreads();
        if (s + 3 < 16) {
            uint32_t off = (uint32_t)(((s + 3) & (NSTAGE - 1)) * STAGE_BYTES);
            int k = (s + 3) * 32;
#pragma unroll
            for (int i = 0; i < 2; i++) {
                cp16(adst[i] + off, asrc[i] + k);
                cp16(bdst[i] + off, bsrc[i] + k);
            }
        }
        CP_COMMIT();

        const uint32_t* As = (const uint32_t*)(dsm + (s & (NSTAGE - 1)) * STAGE_BYTES);
        const uint32_t* Bs = (const uint32_t*)(dsm + (s & (NSTAGE - 1)) * STAGE_BYTES + STG_BYTES);
#pragma unroll
        for (int ks = 0; ks < 2; ks++) {
            const int kq = ks * 8;
            uint32_t a[4][4], b[4][2];
#pragma unroll
            for (int mt = 0; mt < 4; mt++) {
                int row = wm * 64 + mt * 16 + lr;
                a[mt][0] = As[row * (PAD_H / 2) + kq + lc];
                a[mt][1] = As[(row + 8) * (PAD_H / 2) + kq + lc];
                a[mt][2] = As[row * (PAD_H / 2) + kq + lc + 4];
                a[mt][3] = As[(row + 8) * (PAD_H / 2) + kq + lc + 4];
            }
#pragma unroll
            for (int nt = 0; nt < 4; nt++) {
                int col = wn * 32 + nt * 8 + lr;
                b[nt][0] = Bs[col * (PAD_H / 2) + kq + lc];
                b[nt][1] = Bs[col * (PAD_H / 2) + kq + lc + 4];
            }
#pragma unroll
            for (int mt = 0; mt < 4; mt++)
#pragma unroll
                for (int nt = 0; nt < 4; nt++)
                    mma16(acc[mt][nt], a[mt], b[nt]);
        }
    }

    // epilogue: bias + sigmoid, scatter valid rows
#pragma unroll
    for (int mt = 0; mt < 4; mt++) {
        int m = wm * 64 + mt * 16 + lr;
#pragma unroll
        for (int nt = 0; nt < 4; nt++) {
            int n = wn * 32 + nt * 8 + lc * 2;
            float bi0 = bias_s[n], bi1 = bias_s[n + 1];
            if (p0 + m < valid_end) {
                float2 v;
                v.x = 1.f / (1.f + __expf(-(acc[mt][nt][0] + bi0)));
                v.y = 1.f / (1.f + __expf(-(acc[mt][nt][1] + bi1)));
                *(float2*)(out + (size_t)rows_s[m] * D_OUT + n) = v;
            }
            if (p0 + m + 8 < valid_end) {
                float2 v;
                v.x = 1.f / (1.f + __expf(-(acc[mt][nt][2] + bi0)));
                v.y = 1.f / (1.f + __expf(-(acc[mt][nt][3] + bi1)));
                *(float2*)(out + (size_t)rows_s[m + 8] * D_OUT + n) = v;
            }
        }
    }
}

// ---------------- launch ----------------
extern "C" void kernel_launch(void* const* d_in, const int* in_sizes, int n_in,
                              void* d_out, int out_size) {
    const float* x   = (const float*)d_in[0];
    const int*   num = (const int*)d_in[1];
    const int*   c   = (const int*)d_in[2];
    const float* W1  = (const float*)d_in[3];
    const float* b1  = (const float*)d_in[4];
    const float* We  = (const float*)d_in[5];
    const float* be  = (const float*)d_in[6];
    float* out = (float*)d_out;

    static bool attr_done = false;
    if (!attr_done) {
        cudaFuncSetAttribute(gemm1, cudaFuncAttributeMaxDynamicSharedMemorySize, DSMEM_BYTES);
        cudaFuncSetAttribute(gemm2, cudaFuncAttributeMaxDynamicSharedMemorySize, DSMEM_BYTES);
        attr_done = true;
    }

    cvt_x<<<(B_ROWS * D_IN) / (256 * 8), 256>>>(x);

    dim3 tb(32, 8);
    tr_w1<<<dim3(16, 16), tb>>>(W1);
    tr_we<<<dim3(4, 16, 16), tb>>>(We);

    r1_count<<<B_ROWS / 256, 256>>>(num, c);
    r2_scan<<<1, 1>>>();
    r3_scatter<<<B_ROWS / 256, 256>>>(num, c);

    gemm1<<<dim3(4, MT1), 256, DSMEM_BYTES>>>(b1);
    gemm2<<<MT1, 256, DSMEM_BYTES>>>(be, out);
}